// round 15
// baseline (speedup 1.0000x reference)
#include <cuda_runtime.h>
#include <cuda_bf16.h>
#include <cstdint>

#define BB 8
#define NP 1024
#define KK 20
#define EPSBN 1e-5f

typedef unsigned long long u64;

__device__ __forceinline__ float neg_inf() { return __int_as_float(0xff800000); }
__device__ __forceinline__ float pos_inf() { return __int_as_float(0x7f800000); }
__device__ __forceinline__ float lrelu(float v) { return v >= 0.0f ? v : 0.2f * v; }

__device__ __forceinline__ u64 pk2(float lo, float hi) {
    u64 r; asm("mov.b64 %0,{%1,%2};" : "=l"(r) : "f"(lo), "f"(hi)); return r;
}
__device__ __forceinline__ u64 dup2(float v) { return pk2(v, v); }
__device__ __forceinline__ u64 fma2(u64 a, u64 b, u64 c) {
    u64 d; asm("fma.rn.f32x2 %0,%1,%2,%3;" : "=l"(d) : "l"(a), "l"(b), "l"(c)); return d;
}
__device__ __forceinline__ void unpk2(u64 v, float& a, float& b) {
    asm("mov.b64 {%0,%1},%2;" : "=f"(a), "=f"(b) : "l"(v));
}
__device__ __forceinline__ uint32_t smaddr(const void* p) {
    uint32_t a;
    asm("{ .reg .u64 t; cvta.to.shared.u64 t, %1; cvt.u32.u64 %0, t; }" : "=r"(a) : "l"(p));
    return a;
}

#define MMA_BF16(acc, a, b) \
    asm volatile("mma.sync.aligned.m16n8k16.row.col.f32.bf16.bf16.f32 " \
        "{%0,%1,%2,%3}, {%4,%5,%6,%7}, {%8,%9}, {%0,%1,%2,%3};" \
        : "+f"((acc)[0]), "+f"((acc)[1]), "+f"((acc)[2]), "+f"((acc)[3]) \
        : "r"((a)[0]), "r"((a)[1]), "r"((a)[2]), "r"((a)[3]), "r"((b)[0]), "r"((b)[1]))

#define LDSM4(r0, r1, r2, r3, a) \
    asm volatile("ldmatrix.sync.aligned.m8n8.x4.shared.b16 {%0,%1,%2,%3}, [%4];" \
        : "=r"(r0), "=r"(r1), "=r"(r2), "=r"(r3) : "r"(a))

// ---------------- scratch ----------------
__device__ float d_xc[BB * 9 * NP];
__device__ float d_xx[BB * NP];
__device__ float d_nd[(size_t)BB * NP * NP];
__device__ int   d_idx[BB * NP * KK];
__device__ float d_A[(size_t)BB * 256 * NP];
__device__ float d_Bc[(size_t)BB * 256 * NP];
__device__ float d_Mmax[(size_t)BB * 256 * NP];
__device__ float d_hcat[(size_t)BB * 512 * NP];
__device__ float d_h5[(size_t)BB * 1024 * NP];
__device__ float d_cs[1024];
__device__ float d_cs2[1024];
__device__ float d_cs5[1024];
__device__ float d_cs52[1024];
__device__ float d_pooled[BB * 2048];
__device__ float d_h6[BB * 512];
__device__ float d_h7[BB * 256];
__device__ float d_bn0[12];
// split-bf16 operands (h1 = bf16(x), h2 = bf16(x-h1), h3 = bf16(x-h1-h2))
__device__ __nv_bfloat16 d_w5hi[1024 * 512];
__device__ __nv_bfloat16 d_w5lo[1024 * 512];
__device__ __nv_bfloat16 d_hT1[(size_t)BB * NP * 512];
__device__ __nv_bfloat16 d_hT2[(size_t)BB * NP * 512];
__device__ __nv_bfloat16 d_hT3[(size_t)BB * NP * 512];
__device__ __nv_bfloat16 d_xcT1[BB * NP * 16];
__device__ __nv_bfloat16 d_xcT2[BB * NP * 16];
__device__ __nv_bfloat16 d_xcT3[BB * NP * 16];

// ---------------- conv0 ----------------
__global__ void k_conv0_stats(const float* __restrict__ x,
                              const float* __restrict__ w00,
                              const float* __restrict__ w01) {
    int combo = blockIdx.x;             // 0..5 stats, 6..9 zero cs5
    if (combo >= 6) {
        int base = (combo - 6) * 256 + threadIdx.x;
        d_cs5[base] = 0.f; d_cs52[base] = 0.f;
        return;
    }
    int branch = combo >> 1, o = combo & 1;
    int ca, cb; const float* w;
    if (branch == 0)      { ca = 0; cb = 1; w = w00; }   // z
    else if (branch == 1) { ca = 0; cb = 2; w = w01; }   // y
    else                  { ca = 1; cb = 2; w = w01; }   // x (bug-faithful: w0_1)
    float wa = w[o * 2 + 0], wb = w[o * 2 + 1];
    float s = 0.f, s2 = 0.f;
    for (int i = threadIdx.x; i < BB * NP; i += blockDim.x) {
        int b = i >> 10, n = i & 1023;
        float e = wa * x[b * 3 * NP + ca * NP + n] + wb * x[b * 3 * NP + cb * NP + n];
        s += e; s2 += e * e;
    }
    __shared__ float sh[256], sh2[256];
    sh[threadIdx.x] = s; sh2[threadIdx.x] = s2; __syncthreads();
    for (int st = 128; st; st >>= 1) {
        if (threadIdx.x < st) { sh[threadIdx.x] += sh[threadIdx.x + st]; sh2[threadIdx.x] += sh2[threadIdx.x + st]; }
        __syncthreads();
    }
    if (!threadIdx.x) { d_bn0[combo * 2] = sh[0]; d_bn0[combo * 2 + 1] = sh2[0]; }
}

__global__ void k_conv0_build(const float* __restrict__ x,
                              const float* __restrict__ w00, const float* __restrict__ g00, const float* __restrict__ b00,
                              const float* __restrict__ w01, const float* __restrict__ g01, const float* __restrict__ b01) {
    int i = blockIdx.x * blockDim.x + threadIdx.x;
    if (i >= BB * NP) return;
    int b = i >> 10, n = i & 1023;
    float x0 = x[b * 3 * NP + n];
    float x1 = x[b * 3 * NP + NP + n];
    float x2 = x[b * 3 * NP + 2 * NP + n];
    const float inv = 1.0f / (float)(BB * NP);
    float out[6];
    #pragma unroll
    for (int br = 0; br < 3; br++) {
        float xa, xb, mult; const float *w, *g, *bv;
        if (br == 0)      { xa = x0; xb = x1; mult = x2; w = w00; g = g00; bv = b00; }   // z
        else if (br == 1) { xa = x0; xb = x2; mult = x1; w = w01; g = g01; bv = b01; }   // y
        else              { xa = x1; xb = x2; mult = x0; w = w01; g = g01; bv = b01; }   // x
        #pragma unroll
        for (int o = 0; o < 2; o++) {
            float e = w[o * 2] * xa + w[o * 2 + 1] * xb;
            int combo = br * 2 + o;
            float m = d_bn0[combo * 2] * inv;
            float v = d_bn0[combo * 2 + 1] * inv - m * m;
            float sc = g[o] / sqrtf(v + EPSBN);
            out[combo] = lrelu(sc * (e - m) + bv[o]) * mult;
        }
    }
    float ch[9] = { x0, x1, x2, out[4], out[5], out[2], out[3], out[0], out[1] };
    float* xcb = d_xc + b * 9 * NP;
    float xxs = 0.f;
    #pragma unroll
    for (int c = 0; c < 9; c++) { xcb[c * NP + n] = ch[c]; xxs += ch[c] * ch[c]; }
    d_xx[i] = xxs;                       // edge1 ||x||^2
    __nv_bfloat16* t1 = d_xcT1 + (size_t)i * 16;
    __nv_bfloat16* t2 = d_xcT2 + (size_t)i * 16;
    __nv_bfloat16* t3 = d_xcT3 + (size_t)i * 16;
    #pragma unroll
    for (int c = 0; c < 16; c++) {
        float v = (c < 9) ? ch[c] : 0.f;
        __nv_bfloat16 h1 = __float2bfloat16(v);
        float r1 = v - __bfloat162float(h1);
        __nv_bfloat16 h2 = __float2bfloat16(r1);
        t1[c] = h1; t2[c] = h2;
        t3[c] = __float2bfloat16(r1 - __bfloat162float(h2));
    }
}

// dist via HMMA bf16x6 + ldmatrix, symmetric; sequential a-fragment reuse for low regs
#define DW_SMEM (6 * 128 * 72 * 2)
__global__ __launch_bounds__(256, 2) void k_distW(const __nv_bfloat16* __restrict__ th1,
                                               const __nv_bfloat16* __restrict__ th2,
                                               const __nv_bfloat16* __restrict__ th3,
                                               int rs, int cOff, int Cin) {
    extern __shared__ __nv_bfloat16 sm[];
    int tid = threadIdx.x;
    if (blockIdx.x == 0 && blockIdx.y == 0 && blockIdx.z == 0) {
        for (int j = tid; j < 1024; j += 256) { d_cs[j] = 0.f; d_cs2[j] = 0.f; }
    }
    if (blockIdx.y > blockIdx.x) return;          // symmetric: keep ti<=tj
    __nv_bfloat16* sN1 = sm;                   // [128][72] rows = n points
    __nv_bfloat16* sN2 = sm + 9216;
    __nv_bfloat16* sN3 = sm + 18432;
    __nv_bfloat16* sM1 = sm + 27648;           // rows = m points
    __nv_bfloat16* sM2 = sm + 36864;
    __nv_bfloat16* sM3 = sm + 46080;
    uint32_t sb = smaddr(sm);
    int b = blockIdx.z, n0 = blockIdx.y * 128, m0 = blockIdx.x * 128;
    bool diag = (n0 == m0);
    int w = tid >> 5, l = tid & 31;
    int wm = w & 1, wn = w >> 1;
    int r = l >> 2, cq = (l & 3) * 2;
    int aRow = l & 15, aCol = (l >> 4) * 8;
    int bRow = ((l >> 4) << 3) + (l & 7), bCol = ((l >> 3) & 1) * 8;
    uint32_t aB1 = diag ? 55296u : 0u;
    uint32_t aB2 = diag ? 73728u : 18432u;
    uint32_t aB3 = diag ? 92160u : 36864u;
    float acc[4][4][4];
    #pragma unroll
    for (int i = 0; i < 4; i++)
        #pragma unroll
        for (int j = 0; j < 4; j++)
            #pragma unroll
            for (int q = 0; q < 4; q++) acc[i][j][q] = 0.f;

    for (int c0 = 0; c0 < Cin; c0 += 64) {
        #pragma unroll
        for (int q = 0; q < 4; q++) {
            int lin = tid + q * 256;
            int row = lin >> 3, col8 = (lin & 7) * 8;
            int so = row * 72 + col8;
            if (c0 + col8 < Cin) {
                size_t gM = ((size_t)(b * NP + m0 + row)) * rs + cOff + c0 + col8;
                *(uint4*)(sM1 + so) = *(const uint4*)(th1 + gM);
                *(uint4*)(sM2 + so) = *(const uint4*)(th2 + gM);
                *(uint4*)(sM3 + so) = *(const uint4*)(th3 + gM);
                if (!diag) {
                    size_t gN = ((size_t)(b * NP + n0 + row)) * rs + cOff + c0 + col8;
                    *(uint4*)(sN1 + so) = *(const uint4*)(th1 + gN);
                    *(uint4*)(sN2 + so) = *(const uint4*)(th2 + gN);
                    *(uint4*)(sN3 + so) = *(const uint4*)(th3 + gN);
                }
            } else {
                uint4 z = make_uint4(0, 0, 0, 0);
                *(uint4*)(sM1 + so) = z; *(uint4*)(sM2 + so) = z; *(uint4*)(sM3 + so) = z;
                if (!diag) { *(uint4*)(sN1 + so) = z; *(uint4*)(sN2 + so) = z; *(uint4*)(sN3 + so) = z; }
            }
        }
        __syncthreads();
        int nk = (Cin - c0 + 15) >> 4; if (nk > 4) nk = 4;   // skip all-zero k16 steps
        for (int k16 = 0; k16 < nk; k16++) {
            int k0 = k16 * 16;
            uint32_t b1[4][2], b2[4][2], b3[4][2];
            #pragma unroll
            for (int pr = 0; pr < 2; pr++) {
                uint32_t boff = (uint32_t)(((wn * 32 + pr * 16 + bRow) * 72 + k0 + bCol) * 2);
                int p2 = pr * 2;
                LDSM4(b1[p2][0], b1[p2][1], b1[p2 + 1][0], b1[p2 + 1][1], sb + 55296u + boff);
                LDSM4(b2[p2][0], b2[p2][1], b2[p2 + 1][0], b2[p2 + 1][1], sb + 73728u + boff);
                LDSM4(b3[p2][0], b3[p2][1], b3[p2 + 1][0], b3[p2 + 1][1], sb + 92160u + boff);
            }
            #pragma unroll
            for (int mt = 0; mt < 4; mt++) {
                uint32_t aoff = (uint32_t)(((wm * 64 + mt * 16 + aRow) * 72 + k0 + aCol) * 2);
                uint32_t a[4];
                LDSM4(a[0], a[1], a[2], a[3], sb + aB1 + aoff);   // a1
                #pragma unroll
                for (int nt = 0; nt < 4; nt++) {
                    MMA_BF16(acc[mt][nt], a, b1[nt]);
                    MMA_BF16(acc[mt][nt], a, b2[nt]);
                    MMA_BF16(acc[mt][nt], a, b3[nt]);
                }
                LDSM4(a[0], a[1], a[2], a[3], sb + aB2 + aoff);   // a2
                #pragma unroll
                for (int nt = 0; nt < 4; nt++) {
                    MMA_BF16(acc[mt][nt], a, b1[nt]);
                    MMA_BF16(acc[mt][nt], a, b2[nt]);
                }
                LDSM4(a[0], a[1], a[2], a[3], sb + aB3 + aoff);   // a3
                #pragma unroll
                for (int nt = 0; nt < 4; nt++)
                    MMA_BF16(acc[mt][nt], a, b1[nt]);
            }
        }
        __syncthreads();
    }
    float* out = d_nd + (size_t)b * NP * NP;
    bool offdiag = !diag;
    float* st = (float*)sm;                        // [128][129] transpose staging
    #pragma unroll
    for (int mt = 0; mt < 4; mt++) {
        int rrow = wm * 64 + mt * 16 + r;
        int n1 = n0 + rrow;
        float xxn1 = d_xx[b * NP + n1];
        float xxn2 = d_xx[b * NP + n1 + 8];
        #pragma unroll
        for (int nt = 0; nt < 4; nt++) {
            int ccol = wn * 32 + nt * 8 + cq;
            int m = m0 + ccol;
            float xm0 = d_xx[b * NP + m], xm1 = d_xx[b * NP + m + 1];
            float v0 = 2.f * acc[mt][nt][0] - xxn1 - xm0;
            float v1 = 2.f * acc[mt][nt][1] - xxn1 - xm1;
            float v2 = 2.f * acc[mt][nt][2] - xxn2 - xm0;
            float v3 = 2.f * acc[mt][nt][3] - xxn2 - xm1;
            *(float2*)(out + (size_t)n1 * NP + m)       = make_float2(v0, v1);
            *(float2*)(out + (size_t)(n1 + 8) * NP + m) = make_float2(v2, v3);
            if (offdiag) {
                st[rrow * 129 + ccol] = v0; st[rrow * 129 + ccol + 1] = v1;
                st[(rrow + 8) * 129 + ccol] = v2; st[(rrow + 8) * 129 + ccol + 1] = v3;
            }
        }
    }
    if (offdiag) {
        __syncthreads();
        for (int i = tid; i < 128 * 128; i += 256) {
            int mrow = i >> 7, ncol = i & 127;
            out[(size_t)(m0 + mrow) * NP + n0 + ncol] = st[ncol * 129 + mrow];
        }
    }
}

// top-20 per row: float4 scan (ldg), per-lane sorted list + smem head-pointer merge
__global__ void k_knn() {
    __shared__ float s_val[8][21 * 32];
    __shared__ int   s_ind[8][21 * 32];
    int wq   = threadIdx.x >> 5;
    int row  = blockIdx.x * 8 + wq;
    int lane = threadIdx.x & 31;
    const float4* nd4 = (const float4*)(d_nd + (size_t)row * NP);
    float val[KK]; int ind[KK];
    #pragma unroll
    for (int t = 0; t < KK; t++) { val[t] = neg_inf(); ind[t] = 0x7fffffff; }
    for (int m4 = lane; m4 < NP / 4; m4 += 32) {
        float4 v4 = __ldg(nd4 + m4);
        float vv[4] = { v4.x, v4.y, v4.z, v4.w };
        #pragma unroll
        for (int j = 0; j < 4; j++) {
            float v = vv[j];
            if (v > val[KK - 1]) {
                val[KK - 1] = v; ind[KK - 1] = m4 * 4 + j;
                #pragma unroll
                for (int t = KK - 1; t > 0; --t) {
                    if (val[t] > val[t - 1]) {
                        float tv = val[t]; val[t] = val[t - 1]; val[t - 1] = tv;
                        int ti = ind[t]; ind[t] = ind[t - 1]; ind[t - 1] = ti;
                    }
                }
            }
        }
    }
    int base = lane * 21;
    #pragma unroll
    for (int t = 0; t < KK; t++) { s_val[wq][base + t] = val[t]; s_ind[wq][base + t] = ind[t]; }
    __syncwarp();
    int p = 0;
    int* out = d_idx + row * KK;
    for (int r = 0; r < KK; r++) {
        float cv = (p < KK) ? s_val[wq][base + p] : neg_inf();
        int   ci = (p < KK) ? s_ind[wq][base + p] : 0x7fffffff;
        float bv = cv; int bi = ci;
        #pragma unroll
        for (int off = 16; off; off >>= 1) {
            float ov = __shfl_xor_sync(0xffffffffu, bv, off);
            int   oi = __shfl_xor_sync(0xffffffffu, bi, off);
            if (ov > bv || (ov == bv && oi < bi)) { bv = ov; bi = oi; }
        }
        if (bv == cv && bi == ci && p < KK) p++;
        if (lane == 0) out[r] = bi;
    }
}

// ---------------- edge GEMMs: 64(o) x 128(n) tile, dual accumulators, f32x2 ----------------
__global__ __launch_bounds__(256) void k_gemmAB(const float* __restrict__ in, int bs,
                         const float* __restrict__ w, int Cin, int Cout) {
    int b = blockIdx.z;
    int o0 = blockIdx.y * 64, n0 = blockIdx.x * 128;
    __shared__ float su[16][68], sv[16][68], sx[16][132];
    int tid = threadIdx.x;
    int tx = tid & 15, ty = tid >> 4;
    u64 accA[4][4], accB[4][4];
    #pragma unroll
    for (int i = 0; i < 4; i++)
        #pragma unroll
        for (int j = 0; j < 4; j++) { accA[i][j] = 0ull; accB[i][j] = 0ull; }
    const float* xb = in + (size_t)b * bs;
    for (int c0 = 0; c0 < Cin; c0 += 16) {
        {
            int ol = tid >> 2;                // 0..63
            int cb = (tid & 3) * 4;           // 0,4,8,12
            #pragma unroll
            for (int q = 0; q < 4; q++) {
                int c = cb + q;
                float u = 0.f, v = 0.f;
                if (c0 + c < Cin) {
                    u = w[(size_t)(o0 + ol) * (2 * Cin) + c0 + c];
                    v = w[(size_t)(o0 + ol) * (2 * Cin) + Cin + c0 + c] - u;
                }
                su[c][ol] = u; sv[c][ol] = v;
            }
        }
        #pragma unroll
        for (int r = 0; r < 2; r++) {
            int idx = tid + r * 256;
            int kc = idx >> 5, i4 = idx & 31;
            float4 vx = make_float4(0.f, 0.f, 0.f, 0.f);
            if (c0 + kc < Cin)
                vx = *(const float4*)(xb + (size_t)(c0 + kc) * NP + n0 + i4 * 4);
            *(float4*)&sx[kc][i4 * 4] = vx;
        }
        __syncthreads();
        #pragma unroll
        for (int kc = 0; kc < 16; kc++) {
            float4 u4 = *(float4*)&su[kc][ty * 4];
            float4 v4 = *(float4*)&sv[kc][ty * 4];
            float4 b0 = *(float4*)&sx[kc][tx * 8];
            float4 b1 = *(float4*)&sx[kc][tx * 8 + 4];
            u64 bp[4] = { pk2(b0.x, b0.y), pk2(b0.z, b0.w), pk2(b1.x, b1.y), pk2(b1.z, b1.w) };
            float uv[4] = { u4.x, u4.y, u4.z, u4.w };
            float vv[4] = { v4.x, v4.y, v4.z, v4.w };
            #pragma unroll
            for (int i = 0; i < 4; i++) {
                u64 ud = dup2(uv[i]);
                u64 vd = dup2(vv[i]);
                #pragma unroll
                for (int j = 0; j < 4; j++) {
                    accA[i][j] = fma2(ud, bp[j], accA[i][j]);
                    accB[i][j] = fma2(vd, bp[j], accB[i][j]);
                }
            }
        }
        __syncthreads();
    }
    #pragma unroll
    for (int i = 0; i < 4; i++) {
        int o = o0 + ty * 4 + i;
        float a[8], c[8];
        #pragma unroll
        for (int j = 0; j < 4; j++) { unpk2(accA[i][j], a[j * 2], a[j * 2 + 1]); unpk2(accB[i][j], c[j * 2], c[j * 2 + 1]); }
        size_t off = ((size_t)b * Cout + o) * NP + n0 + tx * 8;
        *(float4*)(d_A  + off)     = make_float4(a[0], a[1], a[2], a[3]);
        *(float4*)(d_A  + off + 4) = make_float4(a[4], a[5], a[6], a[7]);
        *(float4*)(d_Bc + off)     = make_float4(c[0], c[1], c[2], c[3]);
        *(float4*)(d_Bc + off + 4) = make_float4(c[4], c[5], c[6], c[7]);
    }
}

// E1: 8 channels per block; As staged transposed [n][12] for float4 gathers
__global__ __launch_bounds__(256) void k_E1(const float* __restrict__ g, int Cout, int zeroXX) {
    int ng = Cout >> 3;
    int b = blockIdx.x / ng, og = (blockIdx.x % ng) * 8;
    if (zeroXX && blockIdx.x == 0) {
        for (int j = threadIdx.x; j < BB * NP; j += 256) d_xx[j] = 0.f;
    }
    __shared__ __align__(16) float As[NP][12];   // cols 0..7 data, 8..11 pad (48KB)
    #pragma unroll
    for (int c = 0; c < 8; c++) {
        const float* src = d_A + ((size_t)b * Cout + og + c) * NP;
        for (int n = threadIdx.x; n < NP; n += 256) As[n][c] = src[n];
    }
    __syncthreads();
    bool useMax[8];
    #pragma unroll
    for (int c = 0; c < 8; c++) useMax[c] = g[og + c] >= 0.f;
    float s[8], s2[8];
    #pragma unroll
    for (int c = 0; c < 8; c++) { s[c] = 0.f; s2[c] = 0.f; }
    for (int n = threadIdx.x; n < NP; n += 256) {
        int ip[KK];
        const int* ib = d_idx + (b * NP + n) * KK;
        #pragma unroll
        for (int kk = 0; kk < KK; kk++) ip[kk] = ib[kk];
        float bc[8];
        #pragma unroll
        for (int c = 0; c < 8; c++) bc[c] = d_Bc[((size_t)b * Cout + og + c) * NP + n];
        float mx[8], mn[8];
        #pragma unroll
        for (int c = 0; c < 8; c++) { mx[c] = neg_inf(); mn[c] = pos_inf(); }
        #pragma unroll
        for (int kk = 0; kk < KK; kk++) {
            float4 a0 = *(const float4*)&As[ip[kk]][0];
            float4 a1 = *(const float4*)&As[ip[kk]][4];
            float av[8] = { a0.x, a0.y, a0.z, a0.w, a1.x, a1.y, a1.z, a1.w };
            #pragma unroll
            for (int c = 0; c < 8; c++) {
                float v = av[c] + bc[c];
                mx[c] = fmaxf(mx[c], v); mn[c] = fminf(mn[c], v);
                s[c] += v; s2[c] += v * v;
            }
        }
        #pragma unroll
        for (int c = 0; c < 8; c++)
            d_Mmax[((size_t)b * Cout + og + c) * NP + n] = useMax[c] ? mx[c] : mn[c];
    }
    int lane = threadIdx.x & 31;
    #pragma unroll
    for (int c = 0; c < 8; c++) {
        float sv = s[c], s2v = s2[c];
        #pragma unroll
        for (int off = 16; off; off >>= 1) {
            sv  += __shfl_xor_sync(0xffffffffu, sv,  off);
            s2v += __shfl_xor_sync(0xffffffffu, s2v, off);
        }
        if (!lane) { atomicAdd(&d_cs[og + c], sv); atomicAdd(&d_cs2[og + c], s2v); }
    }
}

// E3T: fused BN+lrelu + hcat write + split-bf16 transpose (+ optional xx accumulate)
__global__ void k_E3T(const float* __restrict__ g, const float* __restrict__ bv,
                      int Cout, int chOff, float invCnt, int doXX) {
    int b = blockIdx.z, ct = blockIdx.y * 64, n0 = blockIdx.x * 64;
    __shared__ float t[64][65];
    __shared__ float ssc[64], ssh[64];
    int tid = threadIdx.x;
    if (tid < 64) {
        int o = ct + tid;
        float m = d_cs[o] * invCnt;
        float var = d_cs2[o] * invCnt - m * m;
        float sc = g[o] / sqrtf(var + EPSBN);
        ssc[tid] = sc; ssh[tid] = bv[o] - sc * m;
    }
    __syncthreads();
    #pragma unroll
    for (int i = 0; i < 16; i++) {
        int lin = i * 256 + tid;
        int c = lin >> 6, n = lin & 63;
        int o = ct + c;
        float mv = d_Mmax[((size_t)b * Cout + o) * NP + n0 + n];
        float v = lrelu(ssc[c] * mv + ssh[c]);
        d_hcat[(size_t)b * 512 * NP + (size_t)(chOff + o) * NP + n0 + n] = v;
        t[c][n] = v;
    }
    __syncthreads();
    int c0 = chOff + ct;
    #pragma unroll
    for (int i = 0; i < 8; i++) {
        int lin = i * 256 + tid;               // pair index, 2048 total
        int n = lin >> 5, cp = lin & 31;
        float v0 = t[cp * 2][n], v1 = t[cp * 2 + 1][n];
        __nv_bfloat16 a1 = __float2bfloat16(v0);
        __nv_bfloat16 c1 = __float2bfloat16(v1);
        float r0 = v0 - __bfloat162float(a1);
        float r1 = v1 - __bfloat162float(c1);
        __nv_bfloat16 a2 = __float2bfloat16(r0);
        __nv_bfloat16 c2 = __float2bfloat16(r1);
        __nv_bfloat162 p1; p1.x = a1; p1.y = c1;
        __nv_bfloat162 p2; p2.x = a2; p2.y = c2;
        __nv_bfloat162 p3;
        p3.x = __float2bfloat16(r0 - __bfloat162float(a2));
        p3.y = __float2bfloat16(r1 - __bfloat162float(c2));
        size_t off = ((size_t)(b * NP + n0 + n)) * 512 + c0 + cp * 2;
        *(__nv_bfloat162*)(d_hT1 + off) = p1;
        *(__nv_bfloat162*)(d_hT2 + off) = p2;
        *(__nv_bfloat162*)(d_hT3 + off) = p3;
    }
    if (doXX && tid < 64) {
        float s = 0.f;
        #pragma unroll 8
        for (int c = 0; c < 64; c++) { float v = t[c][tid]; s += v * v; }
        atomicAdd(&d_xx[b * NP + n0 + tid], s);
    }
}

// ---------------- split-bf16 helpers ----------------
__global__ void k_w5cvt(const float* __restrict__ w5) {
    int p = blockIdx.x * 256 + threadIdx.x;     // pair index over 1024*512/2
    if (p >= 1024 * 512 / 2) return;
    float2 v = *(const float2*)(w5 + (size_t)p * 2);
    __nv_bfloat16 h0 = __float2bfloat16(v.x);
    __nv_bfloat16 h1 = __float2bfloat16(v.y);
    __nv_bfloat162 hi; hi.x = h0; hi.y = h1;
    __nv_bfloat162 lo;
    lo.x = __float2bfloat16(v.x - __bfloat162float(h0));
    lo.y = __float2bfloat16(v.y - __bfloat162float(h1));
    *(__nv_bfloat162*)(d_w5hi + (size_t)p * 2) = hi;
    *(__nv_bfloat162*)(d_w5lo + (size_t)p * 2) = lo;
}

// 128(o) x 128(n) tile per CTA; ldmatrix; sequential a reuse; fused BN stats (cs5)
#define G5_SMEM (4 * 128 * 72 * 2)

__global__ __launch_bounds__(256, 2) void k_gemm5W() {
    extern __shared__ __nv_bfloat16 sm[];
    __nv_bfloat16* sWhi = sm;                  // [128][72]
    __nv_bfloat16* sWlo = sm + 9216;
    __nv_bfloat16* sHhi = sm + 18432;
    __nv_bfloat16* sHlo = sm + 27648;
    uint32_t sb = smaddr(sm);
    int b = blockIdx.z, o0 = blockIdx.y * 128, n0 = blockIdx.x * 128;
    int tid = threadIdx.x, w = tid >> 5, l = tid & 31;
    int wm = w & 1, wn = w >> 1;
    int r = l >> 2, cq = (l & 3) * 2;
    int aRow = l & 15, aCol = (l >> 4) * 8;
    int bRow = ((l >> 4) << 3) + (l & 7), bCol = ((l >> 3) & 1) * 8;
    float acc[4][4][4];
    #pragma unroll
    for (int i = 0; i < 4; i++)
        #pragma unroll
        for (int j = 0; j < 4; j++)
            #pragma unroll
            for (int q = 0; q < 4; q++) acc[i][j][q] = 0.f;

    for (int ch = 0; ch < 8; ch++) {
        int c0 = ch * 64;
        #pragma unroll
        for (int q = 0; q < 4; q++) {
            int lin = tid + q * 256;
            int row = lin >> 3, col8 = (lin & 7) * 8;
            size_t gW = (size_t)(o0 + row) * 512 + c0 + col8;
            size_t gH = ((size_t)(b * NP + n0 + row)) * 512 + c0 + col8;
            *(uint4*)(sWhi + row * 72 + col8) = *(const uint4*)(d_w5hi + gW);
            *(uint4*)(sWlo + row * 72 + col8) = *(const uint4*)(d_w5lo + gW);
            *(uint4*)(sHhi + row * 72 + col8) = *(const uint4*)(d_hT1 + gH);
            *(uint4*)(sHlo + row * 72 + col8) = *(const uint4*)(d_hT2 + gH);
        }
        __syncthreads();
        #pragma unroll
        for (int k16 = 0; k16 < 4; k16++) {
            int k0 = k16 * 16;
            uint32_t bhi[4][2], blo[4][2];
            #pragma unroll
            for (int pr = 0; pr < 2; pr++) {
                uint32_t boff = (uint32_t)(((wn * 32 + pr * 16 + bRow) * 72 + k0 + bCol) * 2);
                int p2 = pr * 2;
                LDSM4(bhi[p2][0], bhi[p2][1], bhi[p2 + 1][0], bhi[p2 + 1][1], sb + 36864u + boff);
                LDSM4(blo[p2][0], blo[p2][1], blo[p2 + 1][0], blo[p2 + 1][1], sb + 55296u + boff);
            }
            #pragma unroll
            for (int mt = 0; mt < 4; mt++) {
                uint32_t aoff = (uint32_t)(((wm * 64 + mt * 16 + aRow) * 72 + k0 + aCol) * 2);
                uint32_t a[4];
                LDSM4(a[0], a[1], a[2], a[3], sb + aoff);          // Whi
                #pragma unroll
                for (int nt = 0; nt < 4; nt++) {
                    MMA_BF16(acc[mt][nt], a, bhi[nt]);
                    MMA_BF16(acc[mt][nt], a, blo[nt]);
                }
                LDSM4(a[0], a[1], a[2], a[3], sb + 18432u + aoff); // Wlo
                #pragma unroll
                for (int nt = 0; nt < 4; nt++)
                    MMA_BF16(acc[mt][nt], a, bhi[nt]);
            }
        }
        __syncthreads();
    }
    // epilogue: store h5 + fused BN stats
    #pragma unroll
    for (int mt = 0; mt < 4; mt++) {
        int o = o0 + wm * 64 + mt * 16 + r;
        float sA = 0.f, s2A = 0.f, sB = 0.f, s2B = 0.f;
        #pragma unroll
        for (int nt = 0; nt < 4; nt++) {
            int n = n0 + wn * 32 + nt * 8 + cq;
            float c0v = acc[mt][nt][0], c1v = acc[mt][nt][1];
            float c2v = acc[mt][nt][2], c3v = acc[mt][nt][3];
            *(float2*)(d_h5 + ((size_t)b * 1024 + o) * NP + n)     = make_float2(c0v, c1v);
            *(float2*)(d_h5 + ((size_t)b * 1024 + o + 8) * NP + n) = make_float2(c2v, c3v);
            sA += c0v + c1v; s2A += c0v * c0v + c1v * c1v;
            sB += c2v + c3v; s2B += c2v * c2v + c3v * c3v;
        }
        #pragma unroll
        for (int off = 1; off < 4; off <<= 1) {
            sA  += __shfl_xor_sync(0xffffffffu, sA,  off);
            s2A += __shfl_xor_sync(0xffffffffu, s2A, off);
            sB  += __shfl_xor_sync(0xffffffffu, sB,  off);
            s2B += __shfl_xor_sync(0xffffffffu, s2B, off);
        }
        if ((l & 3) == 0) {
            atomicAdd(&d_cs5[o], sA);  atomicAdd(&d_cs52[o], s2A);
            atomicAdd(&d_cs5[o + 8], sB); atomicAdd(&d_cs52[o + 8], s2B);
        }
    }
}

__global__ void k_pool(const float* __restrict__ g, const float* __restrict__ bvv) {
    int o = blockIdx.x, b = blockIdx.y;
    float invCnt = 1.0f / (float)(BB * NP);
    float m = d_cs5[o] * invCnt;
    float var = d_cs52[o] * invCnt - m * m;
    float sc = g[o] / sqrtf(var + EPSBN);
    float sh = bvv[o] - sc * m;
    const float* row = d_h5 + (size_t)b * 1024 * NP + (size_t)o * NP;
    float mx = neg_inf(), s = 0.f;
    for (int n = threadIdx.x; n < NP; n += blockDim.x) {
        float v = lrelu(sc * row[n] + sh);
        mx = fmaxf(mx, v); s += v;
    }
    __shared__ float shm[256], shs[256];
    shm[threadIdx.x] = mx; shs[threadIdx.x] = s; __syncthreads();
    for (int st = 128; st; st >>= 1) {
        if (threadIdx.x < st) {
            shm[threadIdx.x] = fmaxf(shm[threadIdx.x], shm[threadIdx.x + st]);
            shs[threadIdx.x] += shs[threadIdx.x + st];
        }
        __syncthreads();
    }
    if (!threadIdx.x) {
        d_pooled[b * 2048 + o] = shm[0];
        d_pooled[b * 2048 + 1024 + o] = shs[0] / (float)NP;
    }
}

// ---------------- fused FC + batch-BN + lrelu: one block per output channel ----------------
__global__ __launch_bounds__(256) void k_fcbn(const float* __restrict__ in, int inStride,
                                              const float* __restrict__ w, const float* __restrict__ bias,
                                              const float* __restrict__ g, const float* __restrict__ bv,
                                              float* __restrict__ out, int Cin, int Cout) {
    int o = blockIdx.x;
    int wq = threadIdx.x >> 5, lane = threadIdx.x & 31;   // warp = batch element
    const float* wp = w + (size_t)o * Cin;
    const float* ip = in + (size_t)wq * inStride;
    float s = 0.f;
    for (int c = lane; c < Cin; c += 32) s += ip[c] * wp[c];
    #pragma unroll
    for (int off = 16; off; off >>= 1) s += __shfl_xor_sync(0xffffffffu, s, off);
    __shared__ float hv[BB];
    if (!lane) hv[wq] = s + (bias ? bias[o] : 0.0f);
    __syncthreads();
    if (threadIdx.x < BB) {
        float v[BB]; float sm = 0.f;
        #pragma unroll
        for (int b = 0; b < BB; b++) { v[b] = hv[b]; sm += v[b]; }
        float m = sm / (float)BB, s2 = 0.f;
        #pragma unroll
        for (int b = 0; b < BB; b++) { float d = v[b] - m; s2 += d * d; }
        float sc = g[o] / sqrtf(s2 / (float)BB + EPSBN);
        int b = threadIdx.x;
        out[b * Cout + o] = lrelu(sc * (v[b] - m) + bv[o]);
    }
}

__global__ void k_fc(const float* __restrict__ in, int inStride,
                     const float* __restrict__ w, const float* __restrict__ bias,
                     float* __restrict__ out, int Cin, int Cout) {
    int gw = blockIdx.x * (blockDim.x >> 5) + (threadIdx.x >> 5);
    int lane = threadIdx.x & 31;
    if (gw >= BB * Cout) return;
    int b = gw / Cout, o = gw % Cout;
    const float* ip = in + (size_t)b * inStride;
    const float* wp = w + (size_t)o * Cin;
    float s = 0.f;
    for (int c = lane; c < Cin; c += 32) s += ip[c] * wp[c];
    #pragma unroll
    for (int off = 16; off; off >>= 1) s += __shfl_xor_sync(0xffffffffu, s, off);
    if (!lane) out[b * Cout + o] = s + (bias ? bias[o] : 0.0f);
}

// ---------------- host ----------------
static cudaStream_t g_s2;
static cudaEvent_t g_evIn[4], g_evAB[4], g_evW;
static bool g_init = false;

static void ensure_init() {
    if (g_init) return;
    cudaStreamCreateWithFlags(&g_s2, cudaStreamNonBlocking);
    for (int i = 0; i < 4; i++) {
        cudaEventCreateWithFlags(&g_evIn[i], cudaEventDisableTiming);
        cudaEventCreateWithFlags(&g_evAB[i], cudaEventDisableTiming);
    }
    cudaEventCreateWithFlags(&g_evW, cudaEventDisableTiming);
    g_init = true;
}

static void run_edge(const float* in, int inBS, const float* w,
                     const float* g, const float* bv, int Cin, int Cout, int chOff,
                     const __nv_bfloat16* t1, const __nv_bfloat16* t2, const __nv_bfloat16* t3,
                     int rs, int cOff, int CinD, int nextXX, int slot) {
    // fork: gemmAB on side stream (depends only on `in`, ready at this point)
    cudaEventRecord(g_evIn[slot], 0);
    cudaStreamWaitEvent(g_s2, g_evIn[slot], 0);
    k_gemmAB<<<dim3(NP / 128, Cout / 64, BB), 256, 0, g_s2>>>(in, inBS, w, Cin, Cout);
    cudaEventRecord(g_evAB[slot], g_s2);
    // main: dist + knn
    k_distW<<<dim3(8, 8, BB), 256, DW_SMEM>>>(t1, t2, t3, rs, cOff, CinD);
    k_knn<<<BB * NP / 8, 256>>>();
    // join
    cudaStreamWaitEvent(0, g_evAB[slot], 0);
    k_E1<<<BB * (Cout / 8), 256>>>(g, Cout, nextXX);
    k_E3T<<<dim3(16, Cout / 64, BB), 256>>>(g, bv, Cout, chOff,
                                            1.0f / (float)(BB * NP * KK), nextXX);
}

extern "C" void kernel_launch(void* const* d_in, const int* in_sizes, int n_in,
                              void* d_out, int out_size) {
    ensure_init();
    const float* x    = (const float*)d_in[0];
    const float* w00  = (const float*)d_in[1];
    const float* g00  = (const float*)d_in[2];
    const float* b00  = (const float*)d_in[3];
    const float* w01  = (const float*)d_in[4];
    const float* g01  = (const float*)d_in[5];
    const float* b01  = (const float*)d_in[6];
    const float* w1   = (const float*)d_in[7];
    const float* g1   = (const float*)d_in[8];
    const float* b1   = (const float*)d_in[9];
    const float* w2   = (const float*)d_in[10];
    const float* g2   = (const float*)d_in[11];
    const float* b2   = (const float*)d_in[12];
    const float* w3   = (const float*)d_in[13];
    const float* g3   = (const float*)d_in[14];
    const float* b3   = (const float*)d_in[15];
    const float* w4   = (const float*)d_in[16];
    const float* g4   = (const float*)d_in[17];
    const float* b4   = (const float*)d_in[18];
    const float* w5   = (const float*)d_in[19];
    const float* g5   = (const float*)d_in[20];
    const float* b5   = (const float*)d_in[21];
    const float* w6   = (const float*)d_in[22];
    const float* g6   = (const float*)d_in[23];
    const float* b6   = (const float*)d_in[24];
    const float* w7   = (const float*)d_in[25];
    const float* bi7  = (const float*)d_in[26];
    const float* g7   = (const float*)d_in[27];
    const float* b7   = (const float*)d_in[28];
    const float* w8   = (const float*)d_in[29];
    const float* bi8  = (const float*)d_in[30];

    float *xc, *hcat, *pooled, *h6, *h7;
    __nv_bfloat16 *xcT1, *xcT2, *xcT3, *hT1, *hT2, *hT3;
    cudaGetSymbolAddress((void**)&xc,     d_xc);
    cudaGetSymbolAddress((void**)&hcat,   d_hcat);
    cudaGetSymbolAddress((void**)&pooled, d_pooled);
    cudaGetSymbolAddress((void**)&h6,     d_h6);
    cudaGetSymbolAddress((void**)&h7,     d_h7);
    cudaGetSymbolAddress((void**)&xcT1,   d_xcT1);
    cudaGetSymbolAddress((void**)&xcT2,   d_xcT2);
    cudaGetSymbolAddress((void**)&xcT3,   d_xcT3);
    cudaGetSymbolAddress((void**)&hT1,    d_hT1);
    cudaGetSymbolAddress((void**)&hT2,    d_hT2);
    cudaGetSymbolAddress((void**)&hT3,    d_hT3);

    cudaFuncSetAttribute(k_gemm5W, cudaFuncAttributeMaxDynamicSharedMemorySize, G5_SMEM);
    cudaFuncSetAttribute(k_distW,  cudaFuncAttributeMaxDynamicSharedMemorySize, DW_SMEM);

    // w5cvt on side stream, concurrent with conv0 (joined before gemm5W via edge-4 join chain)
    cudaEventRecord(g_evW, 0);
    cudaStreamWaitEvent(g_s2, g_evW, 0);
    k_w5cvt<<<1024, 256, 0, g_s2>>>(w5);

    k_conv0_stats<<<10, 256>>>(x, w00, w01);
    k_conv0_build<<<(BB * NP) / 256, 256>>>(x, w00, g00, b00, w01, g01, b01);

    // edge 1: input xc (9ch fp32, 16ch padded bf16 split transposed)
    run_edge(xc, 9 * NP, w1, g1, b1, 9, 64, 0, xcT1, xcT2, xcT3, 16, 0, 16, 1, 0);
    // edge 2: input x1 = hcat ch 0..63
    run_edge(hcat, 512 * NP, w2, g2, b2, 64, 64, 64, hT1, hT2, hT3, 512, 0, 64, 1, 1);
    // edge 3: input x2 = hcat ch 64..127
    run_edge(hcat + 64 * NP, 512 * NP, w3, g3, b3, 64, 128, 128, hT1, hT2, hT3, 512, 64, 64, 1, 2);
    // edge 4: input x3 = hcat ch 128..255
    run_edge(hcat + 128 * NP, 512 * NP, w4, g4, b4, 128, 256, 256, hT1, hT2, hT3, 512, 128, 128, 0, 3);

    k_gemm5W<<<dim3(8, 8, BB), 256, G5_SMEM>>>();
    k_pool<<<dim3(1024, BB), 256>>>(g5, b5);

    k_fcbn<<<512, 256>>>(pooled, 2048, w6, nullptr, g6, b6, h6, 2048, 512);
    k_fcbn<<<256, 256>>>(h6, 512, w7, bi7, g7, b7, h7, 512, 256);
    k_fc<<<(BB * 40 + 7) / 8, 256>>>(h7, 256, w8, bi8, (float*)d_out, 256, 40);
}

// round 17
// speedup vs baseline: 1.0236x; 1.0236x over previous
#include <cuda_runtime.h>
#include <cuda_bf16.h>
#include <cstdint>

#define BB 8
#define NP 1024
#define KK 20
#define EPSBN 1e-5f

typedef unsigned long long u64;

__device__ __forceinline__ float neg_inf() { return __int_as_float(0xff800000); }
__device__ __forceinline__ float pos_inf() { return __int_as_float(0x7f800000); }
__device__ __forceinline__ float lrelu(float v) { return v >= 0.0f ? v : 0.2f * v; }

__device__ __forceinline__ u64 pk2(float lo, float hi) {
    u64 r; asm("mov.b64 %0,{%1,%2};" : "=l"(r) : "f"(lo), "f"(hi)); return r;
}
__device__ __forceinline__ u64 dup2(float v) { return pk2(v, v); }
__device__ __forceinline__ u64 fma2(u64 a, u64 b, u64 c) {
    u64 d; asm("fma.rn.f32x2 %0,%1,%2,%3;" : "=l"(d) : "l"(a), "l"(b), "l"(c)); return d;
}
__device__ __forceinline__ void unpk2(u64 v, float& a, float& b) {
    asm("mov.b64 {%0,%1},%2;" : "=f"(a), "=f"(b) : "l"(v));
}
__device__ __forceinline__ uint32_t smaddr(const void* p) {
    uint32_t a;
    asm("{ .reg .u64 t; cvta.to.shared.u64 t, %1; cvt.u32.u64 %0, t; }" : "=r"(a) : "l"(p));
    return a;
}

#define MMA_BF16(acc, a, b) \
    asm volatile("mma.sync.aligned.m16n8k16.row.col.f32.bf16.bf16.f32 " \
        "{%0,%1,%2,%3}, {%4,%5,%6,%7}, {%8,%9}, {%0,%1,%2,%3};" \
        : "+f"((acc)[0]), "+f"((acc)[1]), "+f"((acc)[2]), "+f"((acc)[3]) \
        : "r"((a)[0]), "r"((a)[1]), "r"((a)[2]), "r"((a)[3]), "r"((b)[0]), "r"((b)[1]))

#define LDSM4(r0, r1, r2, r3, a) \
    asm volatile("ldmatrix.sync.aligned.m8n8.x4.shared.b16 {%0,%1,%2,%3}, [%4];" \
        : "=r"(r0), "=r"(r1), "=r"(r2), "=r"(r3) : "r"(a))

// ---------------- scratch ----------------
__device__ float d_xc[BB * 9 * NP];
__device__ float d_xx[BB * NP];
__device__ float d_nd[(size_t)BB * NP * NP];
__device__ int   d_idx[BB * NP * KK];
__device__ float d_A[(size_t)BB * 256 * NP];
__device__ float d_Bc[(size_t)BB * 256 * NP];
__device__ float d_Mmax[(size_t)BB * 256 * NP];
__device__ float d_hcat[(size_t)BB * 512 * NP];
__device__ float d_h5[(size_t)BB * 1024 * NP];
__device__ float d_cs[1024];
__device__ float d_cs2[1024];
__device__ float d_cs5[1024];
__device__ float d_cs52[1024];
__device__ float d_pooled[BB * 2048];
__device__ float d_h6[BB * 512];
__device__ float d_h7[BB * 256];
__device__ float d_bn0[12];
// split-bf16 operands (h1 = bf16(x), h2 = bf16(x-h1), h3 = bf16(x-h1-h2))
__device__ __nv_bfloat16 d_w5hi[1024 * 512];
__device__ __nv_bfloat16 d_w5lo[1024 * 512];
__device__ __nv_bfloat16 d_hT1[(size_t)BB * NP * 512];
__device__ __nv_bfloat16 d_hT2[(size_t)BB * NP * 512];
__device__ __nv_bfloat16 d_hT3[(size_t)BB * NP * 512];
__device__ __nv_bfloat16 d_xcT1[BB * NP * 16];
__device__ __nv_bfloat16 d_xcT2[BB * NP * 16];
__device__ __nv_bfloat16 d_xcT3[BB * NP * 16];

// ---------------- conv0 ----------------
__global__ void k_conv0_stats(const float* __restrict__ x,
                              const float* __restrict__ w00,
                              const float* __restrict__ w01) {
    int combo = blockIdx.x;             // 0..5 stats, 6..9 zero cs5
    if (combo >= 6) {
        int base = (combo - 6) * 256 + threadIdx.x;
        d_cs5[base] = 0.f; d_cs52[base] = 0.f;
        return;
    }
    int branch = combo >> 1, o = combo & 1;
    int ca, cb; const float* w;
    if (branch == 0)      { ca = 0; cb = 1; w = w00; }   // z
    else if (branch == 1) { ca = 0; cb = 2; w = w01; }   // y
    else                  { ca = 1; cb = 2; w = w01; }   // x (bug-faithful: w0_1)
    float wa = w[o * 2 + 0], wb = w[o * 2 + 1];
    float s = 0.f, s2 = 0.f;
    for (int i = threadIdx.x; i < BB * NP; i += blockDim.x) {
        int b = i >> 10, n = i & 1023;
        float e = wa * x[b * 3 * NP + ca * NP + n] + wb * x[b * 3 * NP + cb * NP + n];
        s += e; s2 += e * e;
    }
    __shared__ float sh[256], sh2[256];
    sh[threadIdx.x] = s; sh2[threadIdx.x] = s2; __syncthreads();
    for (int st = 128; st; st >>= 1) {
        if (threadIdx.x < st) { sh[threadIdx.x] += sh[threadIdx.x + st]; sh2[threadIdx.x] += sh2[threadIdx.x + st]; }
        __syncthreads();
    }
    if (!threadIdx.x) { d_bn0[combo * 2] = sh[0]; d_bn0[combo * 2 + 1] = sh2[0]; }
}

__global__ void k_conv0_build(const float* __restrict__ x,
                              const float* __restrict__ w00, const float* __restrict__ g00, const float* __restrict__ b00,
                              const float* __restrict__ w01, const float* __restrict__ g01, const float* __restrict__ b01) {
    int i = blockIdx.x * blockDim.x + threadIdx.x;
    if (i >= BB * NP) return;
    int b = i >> 10, n = i & 1023;
    float x0 = x[b * 3 * NP + n];
    float x1 = x[b * 3 * NP + NP + n];
    float x2 = x[b * 3 * NP + 2 * NP + n];
    const float inv = 1.0f / (float)(BB * NP);
    float out[6];
    #pragma unroll
    for (int br = 0; br < 3; br++) {
        float xa, xb, mult; const float *w, *g, *bv;
        if (br == 0)      { xa = x0; xb = x1; mult = x2; w = w00; g = g00; bv = b00; }   // z
        else if (br == 1) { xa = x0; xb = x2; mult = x1; w = w01; g = g01; bv = b01; }   // y
        else              { xa = x1; xb = x2; mult = x0; w = w01; g = g01; bv = b01; }   // x
        #pragma unroll
        for (int o = 0; o < 2; o++) {
            float e = w[o * 2] * xa + w[o * 2 + 1] * xb;
            int combo = br * 2 + o;
            float m = d_bn0[combo * 2] * inv;
            float v = d_bn0[combo * 2 + 1] * inv - m * m;
            float sc = g[o] / sqrtf(v + EPSBN);
            out[combo] = lrelu(sc * (e - m) + bv[o]) * mult;
        }
    }
    float ch[9] = { x0, x1, x2, out[4], out[5], out[2], out[3], out[0], out[1] };
    float* xcb = d_xc + b * 9 * NP;
    float xxs = 0.f;
    #pragma unroll
    for (int c = 0; c < 9; c++) { xcb[c * NP + n] = ch[c]; xxs += ch[c] * ch[c]; }
    d_xx[i] = xxs;                       // edge1 ||x||^2
    __nv_bfloat16* t1 = d_xcT1 + (size_t)i * 16;
    __nv_bfloat16* t2 = d_xcT2 + (size_t)i * 16;
    __nv_bfloat16* t3 = d_xcT3 + (size_t)i * 16;
    #pragma unroll
    for (int c = 0; c < 16; c++) {
        float v = (c < 9) ? ch[c] : 0.f;
        __nv_bfloat16 h1 = __float2bfloat16(v);
        float r1 = v - __bfloat162float(h1);
        __nv_bfloat16 h2 = __float2bfloat16(r1);
        t1[c] = h1; t2[c] = h2;
        t3[c] = __float2bfloat16(r1 - __bfloat162float(h2));
    }
}

// dist via HMMA bf16x6 + ldmatrix, symmetric; sequential a-fragment reuse for low regs
#define DW_SMEM (6 * 128 * 72 * 2)
__global__ __launch_bounds__(256, 2) void k_distW(const __nv_bfloat16* __restrict__ th1,
                                               const __nv_bfloat16* __restrict__ th2,
                                               const __nv_bfloat16* __restrict__ th3,
                                               int rs, int cOff, int Cin) {
    extern __shared__ __nv_bfloat16 sm[];
    int tid = threadIdx.x;
    if (blockIdx.x == 0 && blockIdx.y == 0 && blockIdx.z == 0) {
        for (int j = tid; j < 1024; j += 256) { d_cs[j] = 0.f; d_cs2[j] = 0.f; }
    }
    if (blockIdx.y > blockIdx.x) return;          // symmetric: keep ti<=tj
    __nv_bfloat16* sN1 = sm;                   // [128][72] rows = n points
    __nv_bfloat16* sN2 = sm + 9216;
    __nv_bfloat16* sN3 = sm + 18432;
    __nv_bfloat16* sM1 = sm + 27648;           // rows = m points
    __nv_bfloat16* sM2 = sm + 36864;
    __nv_bfloat16* sM3 = sm + 46080;
    uint32_t sb = smaddr(sm);
    int b = blockIdx.z, n0 = blockIdx.y * 128, m0 = blockIdx.x * 128;
    bool diag = (n0 == m0);
    int w = tid >> 5, l = tid & 31;
    int wm = w & 1, wn = w >> 1;
    int r = l >> 2, cq = (l & 3) * 2;
    int aRow = l & 15, aCol = (l >> 4) * 8;
    int bRow = ((l >> 4) << 3) + (l & 7), bCol = ((l >> 3) & 1) * 8;
    uint32_t aB1 = diag ? 55296u : 0u;
    uint32_t aB2 = diag ? 73728u : 18432u;
    uint32_t aB3 = diag ? 92160u : 36864u;
    float acc[4][4][4];
    #pragma unroll
    for (int i = 0; i < 4; i++)
        #pragma unroll
        for (int j = 0; j < 4; j++)
            #pragma unroll
            for (int q = 0; q < 4; q++) acc[i][j][q] = 0.f;

    for (int c0 = 0; c0 < Cin; c0 += 64) {
        #pragma unroll
        for (int q = 0; q < 4; q++) {
            int lin = tid + q * 256;
            int row = lin >> 3, col8 = (lin & 7) * 8;
            int so = row * 72 + col8;
            if (c0 + col8 < Cin) {
                size_t gM = ((size_t)(b * NP + m0 + row)) * rs + cOff + c0 + col8;
                *(uint4*)(sM1 + so) = *(const uint4*)(th1 + gM);
                *(uint4*)(sM2 + so) = *(const uint4*)(th2 + gM);
                *(uint4*)(sM3 + so) = *(const uint4*)(th3 + gM);
                if (!diag) {
                    size_t gN = ((size_t)(b * NP + n0 + row)) * rs + cOff + c0 + col8;
                    *(uint4*)(sN1 + so) = *(const uint4*)(th1 + gN);
                    *(uint4*)(sN2 + so) = *(const uint4*)(th2 + gN);
                    *(uint4*)(sN3 + so) = *(const uint4*)(th3 + gN);
                }
            } else {
                uint4 z = make_uint4(0, 0, 0, 0);
                *(uint4*)(sM1 + so) = z; *(uint4*)(sM2 + so) = z; *(uint4*)(sM3 + so) = z;
                if (!diag) { *(uint4*)(sN1 + so) = z; *(uint4*)(sN2 + so) = z; *(uint4*)(sN3 + so) = z; }
            }
        }
        __syncthreads();
        int nk = (Cin - c0 + 15) >> 4; if (nk > 4) nk = 4;   // skip all-zero k16 steps
        for (int k16 = 0; k16 < nk; k16++) {
            int k0 = k16 * 16;
            uint32_t b1[4][2], b2[4][2], b3[4][2];
            #pragma unroll
            for (int pr = 0; pr < 2; pr++) {
                uint32_t boff = (uint32_t)(((wn * 32 + pr * 16 + bRow) * 72 + k0 + bCol) * 2);
                int p2 = pr * 2;
                LDSM4(b1[p2][0], b1[p2][1], b1[p2 + 1][0], b1[p2 + 1][1], sb + 55296u + boff);
                LDSM4(b2[p2][0], b2[p2][1], b2[p2 + 1][0], b2[p2 + 1][1], sb + 73728u + boff);
                LDSM4(b3[p2][0], b3[p2][1], b3[p2 + 1][0], b3[p2 + 1][1], sb + 92160u + boff);
            }
            #pragma unroll
            for (int mt = 0; mt < 4; mt++) {
                uint32_t aoff = (uint32_t)(((wm * 64 + mt * 16 + aRow) * 72 + k0 + aCol) * 2);
                uint32_t a[4];
                LDSM4(a[0], a[1], a[2], a[3], sb + aB1 + aoff);   // a1
                #pragma unroll
                for (int nt = 0; nt < 4; nt++) {
                    MMA_BF16(acc[mt][nt], a, b1[nt]);
                    MMA_BF16(acc[mt][nt], a, b2[nt]);
                    MMA_BF16(acc[mt][nt], a, b3[nt]);
                }
                LDSM4(a[0], a[1], a[2], a[3], sb + aB2 + aoff);   // a2
                #pragma unroll
                for (int nt = 0; nt < 4; nt++) {
                    MMA_BF16(acc[mt][nt], a, b1[nt]);
                    MMA_BF16(acc[mt][nt], a, b2[nt]);
                }
                LDSM4(a[0], a[1], a[2], a[3], sb + aB3 + aoff);   // a3
                #pragma unroll
                for (int nt = 0; nt < 4; nt++)
                    MMA_BF16(acc[mt][nt], a, b1[nt]);
            }
        }
        __syncthreads();
    }
    float* out = d_nd + (size_t)b * NP * NP;
    bool offdiag = !diag;
    float* st = (float*)sm;                        // [128][129] transpose staging
    #pragma unroll
    for (int mt = 0; mt < 4; mt++) {
        int rrow = wm * 64 + mt * 16 + r;
        int n1 = n0 + rrow;
        float xxn1 = d_xx[b * NP + n1];
        float xxn2 = d_xx[b * NP + n1 + 8];
        #pragma unroll
        for (int nt = 0; nt < 4; nt++) {
            int ccol = wn * 32 + nt * 8 + cq;
            int m = m0 + ccol;
            float xm0 = d_xx[b * NP + m], xm1 = d_xx[b * NP + m + 1];
            float v0 = 2.f * acc[mt][nt][0] - xxn1 - xm0;
            float v1 = 2.f * acc[mt][nt][1] - xxn1 - xm1;
            float v2 = 2.f * acc[mt][nt][2] - xxn2 - xm0;
            float v3 = 2.f * acc[mt][nt][3] - xxn2 - xm1;
            *(float2*)(out + (size_t)n1 * NP + m)       = make_float2(v0, v1);
            *(float2*)(out + (size_t)(n1 + 8) * NP + m) = make_float2(v2, v3);
            if (offdiag) {
                st[rrow * 129 + ccol] = v0; st[rrow * 129 + ccol + 1] = v1;
                st[(rrow + 8) * 129 + ccol] = v2; st[(rrow + 8) * 129 + ccol + 1] = v3;
            }
        }
    }
    if (offdiag) {
        __syncthreads();
        for (int i = tid; i < 128 * 128; i += 256) {
            int mrow = i >> 7, ncol = i & 127;
            out[(size_t)(m0 + mrow) * NP + n0 + ncol] = st[ncol * 129 + mrow];
        }
    }
}

// top-20 per row: float4 scan (ldg), per-lane sorted list + smem head-pointer merge
__global__ void k_knn() {
    __shared__ float s_val[8][21 * 32];
    __shared__ int   s_ind[8][21 * 32];
    int wq   = threadIdx.x >> 5;
    int row  = blockIdx.x * 8 + wq;
    int lane = threadIdx.x & 31;
    const float4* nd4 = (const float4*)(d_nd + (size_t)row * NP);
    float val[KK]; int ind[KK];
    #pragma unroll
    for (int t = 0; t < KK; t++) { val[t] = neg_inf(); ind[t] = 0x7fffffff; }
    for (int m4 = lane; m4 < NP / 4; m4 += 32) {
        float4 v4 = __ldg(nd4 + m4);
        float vv[4] = { v4.x, v4.y, v4.z, v4.w };
        #pragma unroll
        for (int j = 0; j < 4; j++) {
            float v = vv[j];
            if (v > val[KK - 1]) {
                val[KK - 1] = v; ind[KK - 1] = m4 * 4 + j;
                #pragma unroll
                for (int t = KK - 1; t > 0; --t) {
                    if (val[t] > val[t - 1]) {
                        float tv = val[t]; val[t] = val[t - 1]; val[t - 1] = tv;
                        int ti = ind[t]; ind[t] = ind[t - 1]; ind[t - 1] = ti;
                    }
                }
            }
        }
    }
    int base = lane * 21;
    #pragma unroll
    for (int t = 0; t < KK; t++) { s_val[wq][base + t] = val[t]; s_ind[wq][base + t] = ind[t]; }
    __syncwarp();
    int p = 0;
    int* out = d_idx + row * KK;
    for (int r = 0; r < KK; r++) {
        float cv = (p < KK) ? s_val[wq][base + p] : neg_inf();
        int   ci = (p < KK) ? s_ind[wq][base + p] : 0x7fffffff;
        float bv = cv; int bi = ci;
        #pragma unroll
        for (int off = 16; off; off >>= 1) {
            float ov = __shfl_xor_sync(0xffffffffu, bv, off);
            int   oi = __shfl_xor_sync(0xffffffffu, bi, off);
            if (ov > bv || (ov == bv && oi < bi)) { bv = ov; bi = oi; }
        }
        if (bv == cv && bi == ci && p < KK) p++;
        if (lane == 0) out[r] = bi;
    }
}

// ---------------- edge GEMMs: 64(o) x 128(n) tile, dual accumulators, f32x2 ----------------
__global__ __launch_bounds__(256) void k_gemmAB(const float* __restrict__ in, int bs,
                         const float* __restrict__ w, int Cin, int Cout) {
    int b = blockIdx.z;
    int o0 = blockIdx.y * 64, n0 = blockIdx.x * 128;
    __shared__ float su[16][68], sv[16][68], sx[16][132];
    int tid = threadIdx.x;
    int tx = tid & 15, ty = tid >> 4;
    u64 accA[4][4], accB[4][4];
    #pragma unroll
    for (int i = 0; i < 4; i++)
        #pragma unroll
        for (int j = 0; j < 4; j++) { accA[i][j] = 0ull; accB[i][j] = 0ull; }
    const float* xb = in + (size_t)b * bs;
    for (int c0 = 0; c0 < Cin; c0 += 16) {
        {
            int ol = tid >> 2;                // 0..63
            int cb = (tid & 3) * 4;           // 0,4,8,12
            #pragma unroll
            for (int q = 0; q < 4; q++) {
                int c = cb + q;
                float u = 0.f, v = 0.f;
                if (c0 + c < Cin) {
                    u = w[(size_t)(o0 + ol) * (2 * Cin) + c0 + c];
                    v = w[(size_t)(o0 + ol) * (2 * Cin) + Cin + c0 + c] - u;
                }
                su[c][ol] = u; sv[c][ol] = v;
            }
        }
        #pragma unroll
        for (int r = 0; r < 2; r++) {
            int idx = tid + r * 256;
            int kc = idx >> 5, i4 = idx & 31;
            float4 vx = make_float4(0.f, 0.f, 0.f, 0.f);
            if (c0 + kc < Cin)
                vx = *(const float4*)(xb + (size_t)(c0 + kc) * NP + n0 + i4 * 4);
            *(float4*)&sx[kc][i4 * 4] = vx;
        }
        __syncthreads();
        #pragma unroll
        for (int kc = 0; kc < 16; kc++) {
            float4 u4 = *(float4*)&su[kc][ty * 4];
            float4 v4 = *(float4*)&sv[kc][ty * 4];
            float4 b0 = *(float4*)&sx[kc][tx * 8];
            float4 b1 = *(float4*)&sx[kc][tx * 8 + 4];
            u64 bp[4] = { pk2(b0.x, b0.y), pk2(b0.z, b0.w), pk2(b1.x, b1.y), pk2(b1.z, b1.w) };
            float uv[4] = { u4.x, u4.y, u4.z, u4.w };
            float vv[4] = { v4.x, v4.y, v4.z, v4.w };
            #pragma unroll
            for (int i = 0; i < 4; i++) {
                u64 ud = dup2(uv[i]);
                u64 vd = dup2(vv[i]);
                #pragma unroll
                for (int j = 0; j < 4; j++) {
                    accA[i][j] = fma2(ud, bp[j], accA[i][j]);
                    accB[i][j] = fma2(vd, bp[j], accB[i][j]);
                }
            }
        }
        __syncthreads();
    }
    #pragma unroll
    for (int i = 0; i < 4; i++) {
        int o = o0 + ty * 4 + i;
        float a[8], c[8];
        #pragma unroll
        for (int j = 0; j < 4; j++) { unpk2(accA[i][j], a[j * 2], a[j * 2 + 1]); unpk2(accB[i][j], c[j * 2], c[j * 2 + 1]); }
        size_t off = ((size_t)b * Cout + o) * NP + n0 + tx * 8;
        *(float4*)(d_A  + off)     = make_float4(a[0], a[1], a[2], a[3]);
        *(float4*)(d_A  + off + 4) = make_float4(a[4], a[5], a[6], a[7]);
        *(float4*)(d_Bc + off)     = make_float4(c[0], c[1], c[2], c[3]);
        *(float4*)(d_Bc + off + 4) = make_float4(c[4], c[5], c[6], c[7]);
    }
}

// E1: 8 channels per block; idx row loaded once; block 0 optionally zeroes d_xx
__global__ __launch_bounds__(256) void k_E1(const float* __restrict__ g, int Cout, int zeroXX) {
    int ng = Cout >> 3;
    int b = blockIdx.x / ng, og = (blockIdx.x % ng) * 8;
    if (zeroXX && blockIdx.x == 0) {
        for (int j = threadIdx.x; j < BB * NP; j += 256) d_xx[j] = 0.f;
    }
    __shared__ float As[8][NP];
    for (int i = threadIdx.x; i < 8 * NP; i += 256)
        As[i >> 10][i & 1023] = d_A[((size_t)b * Cout + og + (i >> 10)) * NP + (i & 1023)];
    __syncthreads();
    bool useMax[8];
    #pragma unroll
    for (int c = 0; c < 8; c++) useMax[c] = g[og + c] >= 0.f;
    float s[8], s2[8];
    #pragma unroll
    for (int c = 0; c < 8; c++) { s[c] = 0.f; s2[c] = 0.f; }
    for (int n = threadIdx.x; n < NP; n += 256) {
        int ip[KK];
        const int* ib = d_idx + (b * NP + n) * KK;
        #pragma unroll
        for (int kk = 0; kk < KK; kk++) ip[kk] = ib[kk];
        #pragma unroll
        for (int c = 0; c < 8; c++) {
            float bc = d_Bc[((size_t)b * Cout + og + c) * NP + n];
            float mx = neg_inf(), mn = pos_inf();
            #pragma unroll
            for (int kk = 0; kk < KK; kk++) {
                float v = As[c][ip[kk]] + bc;
                mx = fmaxf(mx, v); mn = fminf(mn, v);
                s[c] += v; s2[c] += v * v;
            }
            d_Mmax[((size_t)b * Cout + og + c) * NP + n] = useMax[c] ? mx : mn;
        }
    }
    int lane = threadIdx.x & 31;
    #pragma unroll
    for (int c = 0; c < 8; c++) {
        float sv = s[c], s2v = s2[c];
        #pragma unroll
        for (int off = 16; off; off >>= 1) {
            sv  += __shfl_xor_sync(0xffffffffu, sv,  off);
            s2v += __shfl_xor_sync(0xffffffffu, s2v, off);
        }
        if (!lane) { atomicAdd(&d_cs[og + c], sv); atomicAdd(&d_cs2[og + c], s2v); }
    }
}

// E3T: fused BN+lrelu + hcat write + split-bf16 transpose (+ optional xx accumulate)
__global__ void k_E3T(const float* __restrict__ g, const float* __restrict__ bv,
                      int Cout, int chOff, float invCnt, int doXX) {
    int b = blockIdx.z, ct = blockIdx.y * 64, n0 = blockIdx.x * 64;
    __shared__ float t[64][65];
    __shared__ float ssc[64], ssh[64];
    int tid = threadIdx.x;
    if (tid < 64) {
        int o = ct + tid;
        float m = d_cs[o] * invCnt;
        float var = d_cs2[o] * invCnt - m * m;
        float sc = g[o] / sqrtf(var + EPSBN);
        ssc[tid] = sc; ssh[tid] = bv[o] - sc * m;
    }
    __syncthreads();
    #pragma unroll
    for (int i = 0; i < 16; i++) {
        int lin = i * 256 + tid;
        int c = lin >> 6, n = lin & 63;
        int o = ct + c;
        float mv = d_Mmax[((size_t)b * Cout + o) * NP + n0 + n];
        float v = lrelu(ssc[c] * mv + ssh[c]);
        d_hcat[(size_t)b * 512 * NP + (size_t)(chOff + o) * NP + n0 + n] = v;
        t[c][n] = v;
    }
    __syncthreads();
    int c0 = chOff + ct;
    #pragma unroll
    for (int i = 0; i < 8; i++) {
        int lin = i * 256 + tid;               // pair index, 2048 total
        int n = lin >> 5, cp = lin & 31;
        float v0 = t[cp * 2][n], v1 = t[cp * 2 + 1][n];
        __nv_bfloat16 a1 = __float2bfloat16(v0);
        __nv_bfloat16 c1 = __float2bfloat16(v1);
        float r0 = v0 - __bfloat162float(a1);
        float r1 = v1 - __bfloat162float(c1);
        __nv_bfloat16 a2 = __float2bfloat16(r0);
        __nv_bfloat16 c2 = __float2bfloat16(r1);
        __nv_bfloat162 p1; p1.x = a1; p1.y = c1;
        __nv_bfloat162 p2; p2.x = a2; p2.y = c2;
        __nv_bfloat162 p3;
        p3.x = __float2bfloat16(r0 - __bfloat162float(a2));
        p3.y = __float2bfloat16(r1 - __bfloat162float(c2));
        size_t off = ((size_t)(b * NP + n0 + n)) * 512 + c0 + cp * 2;
        *(__nv_bfloat162*)(d_hT1 + off) = p1;
        *(__nv_bfloat162*)(d_hT2 + off) = p2;
        *(__nv_bfloat162*)(d_hT3 + off) = p3;
    }
    if (doXX && tid < 64) {
        float s = 0.f;
        #pragma unroll 8
        for (int c = 0; c < 64; c++) { float v = t[c][tid]; s += v * v; }
        atomicAdd(&d_xx[b * NP + n0 + tid], s);
    }
}

// ---------------- split-bf16 helpers ----------------
__global__ void k_w5cvt(const float* __restrict__ w5) {
    int p = blockIdx.x * 256 + threadIdx.x;     // pair index over 1024*512/2
    if (p >= 1024 * 512 / 2) return;
    float2 v = *(const float2*)(w5 + (size_t)p * 2);
    __nv_bfloat16 h0 = __float2bfloat16(v.x);
    __nv_bfloat16 h1 = __float2bfloat16(v.y);
    __nv_bfloat162 hi; hi.x = h0; hi.y = h1;
    __nv_bfloat162 lo;
    lo.x = __float2bfloat16(v.x - __bfloat162float(h0));
    lo.y = __float2bfloat16(v.y - __bfloat162float(h1));
    *(__nv_bfloat162*)(d_w5hi + (size_t)p * 2) = hi;
    *(__nv_bfloat162*)(d_w5lo + (size_t)p * 2) = lo;
}

// 128(o) x 128(n) tile per CTA; ldmatrix; sequential a reuse; fused BN stats (cs5)
#define G5_SMEM (4 * 128 * 72 * 2)

__global__ __launch_bounds__(256, 2) void k_gemm5W() {
    extern __shared__ __nv_bfloat16 sm[];
    __nv_bfloat16* sWhi = sm;                  // [128][72]
    __nv_bfloat16* sWlo = sm + 9216;
    __nv_bfloat16* sHhi = sm + 18432;
    __nv_bfloat16* sHlo = sm + 27648;
    uint32_t sb = smaddr(sm);
    int b = blockIdx.z, o0 = blockIdx.y * 128, n0 = blockIdx.x * 128;
    int tid = threadIdx.x, w = tid >> 5, l = tid & 31;
    int wm = w & 1, wn = w >> 1;
    int r = l >> 2, cq = (l & 3) * 2;
    int aRow = l & 15, aCol = (l >> 4) * 8;
    int bRow = ((l >> 4) << 3) + (l & 7), bCol = ((l >> 3) & 1) * 8;
    float acc[4][4][4];
    #pragma unroll
    for (int i = 0; i < 4; i++)
        #pragma unroll
        for (int j = 0; j < 4; j++)
            #pragma unroll
            for (int q = 0; q < 4; q++) acc[i][j][q] = 0.f;

    for (int ch = 0; ch < 8; ch++) {
        int c0 = ch * 64;
        #pragma unroll
        for (int q = 0; q < 4; q++) {
            int lin = tid + q * 256;
            int row = lin >> 3, col8 = (lin & 7) * 8;
            size_t gW = (size_t)(o0 + row) * 512 + c0 + col8;
            size_t gH = ((size_t)(b * NP + n0 + row)) * 512 + c0 + col8;
            *(uint4*)(sWhi + row * 72 + col8) = *(const uint4*)(d_w5hi + gW);
            *(uint4*)(sWlo + row * 72 + col8) = *(const uint4*)(d_w5lo + gW);
            *(uint4*)(sHhi + row * 72 + col8) = *(const uint4*)(d_hT1 + gH);
            *(uint4*)(sHlo + row * 72 + col8) = *(const uint4*)(d_hT2 + gH);
        }
        __syncthreads();
        #pragma unroll
        for (int k16 = 0; k16 < 4; k16++) {
            int k0 = k16 * 16;
            uint32_t bhi[4][2], blo[4][2];
            #pragma unroll
            for (int pr = 0; pr < 2; pr++) {
                uint32_t boff = (uint32_t)(((wn * 32 + pr * 16 + bRow) * 72 + k0 + bCol) * 2);
                int p2 = pr * 2;
                LDSM4(bhi[p2][0], bhi[p2][1], bhi[p2 + 1][0], bhi[p2 + 1][1], sb + 36864u + boff);
                LDSM4(blo[p2][0], blo[p2][1], blo[p2 + 1][0], blo[p2 + 1][1], sb + 55296u + boff);
            }
            #pragma unroll
            for (int mt = 0; mt < 4; mt++) {
                uint32_t aoff = (uint32_t)(((wm * 64 + mt * 16 + aRow) * 72 + k0 + aCol) * 2);
                uint32_t a[4];
                LDSM4(a[0], a[1], a[2], a[3], sb + aoff);          // Whi
                #pragma unroll
                for (int nt = 0; nt < 4; nt++) {
                    MMA_BF16(acc[mt][nt], a, bhi[nt]);
                    MMA_BF16(acc[mt][nt], a, blo[nt]);
                }
                LDSM4(a[0], a[1], a[2], a[3], sb + 18432u + aoff); // Wlo
                #pragma unroll
                for (int nt = 0; nt < 4; nt++)
                    MMA_BF16(acc[mt][nt], a, bhi[nt]);
            }
        }
        __syncthreads();
    }
    // epilogue: store h5 + fused BN stats
    #pragma unroll
    for (int mt = 0; mt < 4; mt++) {
        int o = o0 + wm * 64 + mt * 16 + r;
        float sA = 0.f, s2A = 0.f, sB = 0.f, s2B = 0.f;
        #pragma unroll
        for (int nt = 0; nt < 4; nt++) {
            int n = n0 + wn * 32 + nt * 8 + cq;
            float c0v = acc[mt][nt][0], c1v = acc[mt][nt][1];
            float c2v = acc[mt][nt][2], c3v = acc[mt][nt][3];
            *(float2*)(d_h5 + ((size_t)b * 1024 + o) * NP + n)     = make_float2(c0v, c1v);
            *(float2*)(d_h5 + ((size_t)b * 1024 + o + 8) * NP + n) = make_float2(c2v, c3v);
            sA += c0v + c1v; s2A += c0v * c0v + c1v * c1v;
            sB += c2v + c3v; s2B += c2v * c2v + c3v * c3v;
        }
        #pragma unroll
        for (int off = 1; off < 4; off <<= 1) {
            sA  += __shfl_xor_sync(0xffffffffu, sA,  off);
            s2A += __shfl_xor_sync(0xffffffffu, s2A, off);
            sB  += __shfl_xor_sync(0xffffffffu, sB,  off);
            s2B += __shfl_xor_sync(0xffffffffu, s2B, off);
        }
        if ((l & 3) == 0) {
            atomicAdd(&d_cs5[o], sA);  atomicAdd(&d_cs52[o], s2A);
            atomicAdd(&d_cs5[o + 8], sB); atomicAdd(&d_cs52[o + 8], s2B);
        }
    }
}

// pool: one warp per (o,b) row; shfl-only reduction, no smem barriers
__global__ __launch_bounds__(256) void k_pool(const float* __restrict__ g, const float* __restrict__ bvv) {
    int wq = threadIdx.x >> 5, lane = threadIdx.x & 31;
    int idx = blockIdx.x * 8 + wq;              // 0..8191
    int o = idx >> 3, b = idx & 7;
    float invCnt = 1.0f / (float)(BB * NP);
    float m = d_cs5[o] * invCnt;
    float var = d_cs52[o] * invCnt - m * m;
    float sc = g[o] / sqrtf(var + EPSBN);
    float sh = bvv[o] - sc * m;
    const float4* row = (const float4*)(d_h5 + ((size_t)b * 1024 + o) * NP);
    float mx = neg_inf(), s = 0.f;
    #pragma unroll
    for (int i = 0; i < 8; i++) {
        float4 v4 = __ldg(row + i * 32 + lane);
        float a0 = lrelu(sc * v4.x + sh);
        float a1 = lrelu(sc * v4.y + sh);
        float a2 = lrelu(sc * v4.z + sh);
        float a3 = lrelu(sc * v4.w + sh);
        mx = fmaxf(mx, fmaxf(fmaxf(a0, a1), fmaxf(a2, a3)));
        s += (a0 + a1) + (a2 + a3);
    }
    #pragma unroll
    for (int off = 16; off; off >>= 1) {
        mx = fmaxf(mx, __shfl_xor_sync(0xffffffffu, mx, off));
        s += __shfl_xor_sync(0xffffffffu, s, off);
    }
    if (!lane) {
        d_pooled[b * 2048 + o] = mx;
        d_pooled[b * 2048 + 1024 + o] = s / (float)NP;
    }
}

// ---------------- fused FC + batch-BN + lrelu: one block per output channel ----------------
__global__ __launch_bounds__(256) void k_fcbn(const float* __restrict__ in, int inStride,
                                              const float* __restrict__ w, const float* __restrict__ bias,
                                              const float* __restrict__ g, const float* __restrict__ bv,
                                              float* __restrict__ out, int Cin, int Cout) {
    int o = blockIdx.x;
    int wq = threadIdx.x >> 5, lane = threadIdx.x & 31;   // warp = batch element
    const float* wp = w + (size_t)o * Cin;
    const float* ip = in + (size_t)wq * inStride;
    float s = 0.f;
    for (int c = lane; c < Cin; c += 32) s += ip[c] * wp[c];
    #pragma unroll
    for (int off = 16; off; off >>= 1) s += __shfl_xor_sync(0xffffffffu, s, off);
    __shared__ float hv[BB];
    if (!lane) hv[wq] = s + (bias ? bias[o] : 0.0f);
    __syncthreads();
    if (threadIdx.x < BB) {
        float v[BB]; float sm = 0.f;
        #pragma unroll
        for (int b = 0; b < BB; b++) { v[b] = hv[b]; sm += v[b]; }
        float m = sm / (float)BB, s2 = 0.f;
        #pragma unroll
        for (int b = 0; b < BB; b++) { float d = v[b] - m; s2 += d * d; }
        float sc = g[o] / sqrtf(s2 / (float)BB + EPSBN);
        int b = threadIdx.x;
        out[b * Cout + o] = lrelu(sc * (v[b] - m) + bv[o]);
    }
}

__global__ void k_fc(const float* __restrict__ in, int inStride,
                     const float* __restrict__ w, const float* __restrict__ bias,
                     float* __restrict__ out, int Cin, int Cout) {
    int gw = blockIdx.x * (blockDim.x >> 5) + (threadIdx.x >> 5);
    int lane = threadIdx.x & 31;
    if (gw >= BB * Cout) return;
    int b = gw / Cout, o = gw % Cout;
    const float* ip = in + (size_t)b * inStride;
    const float* wp = w + (size_t)o * Cin;
    float s = 0.f;
    for (int c = lane; c < Cin; c += 32) s += ip[c] * wp[c];
    #pragma unroll
    for (int off = 16; off; off >>= 1) s += __shfl_xor_sync(0xffffffffu, s, off);
    if (!lane) out[b * Cout + o] = s + (bias ? bias[o] : 0.0f);
}

// ---------------- host ----------------
static cudaStream_t g_s2;
static cudaEvent_t g_evIn[4], g_evAB[4], g_evW;
static bool g_init = false;

static void ensure_init() {
    if (g_init) return;
    cudaStreamCreateWithFlags(&g_s2, cudaStreamNonBlocking);
    for (int i = 0; i < 4; i++) {
        cudaEventCreateWithFlags(&g_evIn[i], cudaEventDisableTiming);
        cudaEventCreateWithFlags(&g_evAB[i], cudaEventDisableTiming);
    }
    cudaEventCreateWithFlags(&g_evW, cudaEventDisableTiming);
    g_init = true;
}

static void run_edge(const float* in, int inBS, const float* w,
                     const float* g, const float* bv, int Cin, int Cout, int chOff,
                     const __nv_bfloat16* t1, const __nv_bfloat16* t2, const __nv_bfloat16* t3,
                     int rs, int cOff, int CinD, int nextXX, int slot) {
    // fork: gemmAB on side stream (depends only on `in`, ready at this point)
    cudaEventRecord(g_evIn[slot], 0);
    cudaStreamWaitEvent(g_s2, g_evIn[slot], 0);
    k_gemmAB<<<dim3(NP / 128, Cout / 64, BB), 256, 0, g_s2>>>(in, inBS, w, Cin, Cout);
    cudaEventRecord(g_evAB[slot], g_s2);
    // main: dist + knn
    k_distW<<<dim3(8, 8, BB), 256, DW_SMEM>>>(t1, t2, t3, rs, cOff, CinD);
    k_knn<<<BB * NP / 8, 256>>>();
    // join
    cudaStreamWaitEvent(0, g_evAB[slot], 0);
    k_E1<<<BB * (Cout / 8), 256>>>(g, Cout, nextXX);
    k_E3T<<<dim3(16, Cout / 64, BB), 256>>>(g, bv, Cout, chOff,
                                            1.0f / (float)(BB * NP * KK), nextXX);
}

extern "C" void kernel_launch(void* const* d_in, const int* in_sizes, int n_in,
                              void* d_out, int out_size) {
    ensure_init();
    const float* x    = (const float*)d_in[0];
    const float* w00  = (const float*)d_in[1];
    const float* g00  = (const float*)d_in[2];
    const float* b00  = (const float*)d_in[3];
    const float* w01  = (const float*)d_in[4];
    const float* g01  = (const float*)d_in[5];
    const float* b01  = (const float*)d_in[6];
    const float* w1   = (const float*)d_in[7];
    const float* g1   = (const float*)d_in[8];
    const float* b1   = (const float*)d_in[9];
    const float* w2   = (const float*)d_in[10];
    const float* g2   = (const float*)d_in[11];
    const float* b2   = (const float*)d_in[12];
    const float* w3   = (const float*)d_in[13];
    const float* g3   = (const float*)d_in[14];
    const float* b3   = (const float*)d_in[15];
    const float* w4   = (const float*)d_in[16];
    const float* g4   = (const float*)d_in[17];
    const float* b4   = (const float*)d_in[18];
    const float* w5   = (const float*)d_in[19];
    const float* g5   = (const float*)d_in[20];
    const float* b5   = (const float*)d_in[21];
    const float* w6   = (const float*)d_in[22];
    const float* g6   = (const float*)d_in[23];
    const float* b6   = (const float*)d_in[24];
    const float* w7   = (const float*)d_in[25];
    const float* bi7  = (const float*)d_in[26];
    const float* g7   = (const float*)d_in[27];
    const float* b7   = (const float*)d_in[28];
    const float* w8   = (const float*)d_in[29];
    const float* bi8  = (const float*)d_in[30];

    float *xc, *hcat, *pooled, *h6, *h7;
    __nv_bfloat16 *xcT1, *xcT2, *xcT3, *hT1, *hT2, *hT3;
    cudaGetSymbolAddress((void**)&xc,     d_xc);
    cudaGetSymbolAddress((void**)&hcat,   d_hcat);
    cudaGetSymbolAddress((void**)&pooled, d_pooled);
    cudaGetSymbolAddress((void**)&h6,     d_h6);
    cudaGetSymbolAddress((void**)&h7,     d_h7);
    cudaGetSymbolAddress((void**)&xcT1,   d_xcT1);
    cudaGetSymbolAddress((void**)&xcT2,   d_xcT2);
    cudaGetSymbolAddress((void**)&xcT3,   d_xcT3);
    cudaGetSymbolAddress((void**)&hT1,    d_hT1);
    cudaGetSymbolAddress((void**)&hT2,    d_hT2);
    cudaGetSymbolAddress((void**)&hT3,    d_hT3);

    cudaFuncSetAttribute(k_gemm5W, cudaFuncAttributeMaxDynamicSharedMemorySize, G5_SMEM);
    cudaFuncSetAttribute(k_distW,  cudaFuncAttributeMaxDynamicSharedMemorySize, DW_SMEM);

    // w5cvt on side stream, concurrent with conv0 (joined before gemm5W via edge-4 join chain)
    cudaEventRecord(g_evW, 0);
    cudaStreamWaitEvent(g_s2, g_evW, 0);
    k_w5cvt<<<1024, 256, 0, g_s2>>>(w5);

    k_conv0_stats<<<10, 256>>>(x, w00, w01);
    k_conv0_build<<<(BB * NP) / 256, 256>>>(x, w00, g00, b00, w01, g01, b01);

    // edge 1: input xc (9ch fp32, 16ch padded bf16 split transposed)
    run_edge(xc, 9 * NP, w1, g1, b1, 9, 64, 0, xcT1, xcT2, xcT3, 16, 0, 16, 1, 0);
    // edge 2: input x1 = hcat ch 0..63
    run_edge(hcat, 512 * NP, w2, g2, b2, 64, 64, 64, hT1, hT2, hT3, 512, 0, 64, 1, 1);
    // edge 3: input x2 = hcat ch 64..127
    run_edge(hcat + 64 * NP, 512 * NP, w3, g3, b3, 64, 128, 128, hT1, hT2, hT3, 512, 64, 64, 1, 2);
    // edge 4: input x3 = hcat ch 128..255
    run_edge(hcat + 128 * NP, 512 * NP, w4, g4, b4, 128, 256, 256, hT1, hT2, hT3, 512, 128, 128, 0, 3);

    k_gemm5W<<<dim3(8, 8, BB), 256, G5_SMEM>>>();
    k_pool<<<1024, 256>>>(g5, b5);

    k_fcbn<<<512, 256>>>(pooled, 2048, w6, nullptr, g6, b6, h6, 2048, 512);
    k_fcbn<<<256, 256>>>(h6, 512, w7, bi7, g7, b7, h7, 512, 256);
    k_fc<<<(BB * 40 + 7) / 8, 256>>>(h7, 256, w8, bi8, (float*)d_out, 256, 40);
}